// round 5
// baseline (speedup 1.0000x reference)
#include <cuda_runtime.h>

// ---------------- problem constants ----------------
#define WN_WINDOWS 960
#define P_TOK      144
#define DIMC       192
#define HEADS      6
#define DH         32
#define NQKV       576          // 3*DIM
#define MROWS      138240       // 960*144
#define QK_SCALE   0.17677669529663687f   // 32^-0.5

// bias table geometry: (3312, 64, 6); stride over idx = 64*6 = 384
#define BT_STRIDE  384

// ---------------- scratch (static device globals; no alloc allowed) -----
__device__ float g_qkv[(size_t)MROWS * NQKV];   // (BN*P, 3*DIM)
__device__ float g_att[(size_t)MROWS * DIMC];   // (BN*P, DIM) attention output

// ---------------- fp32 GEMM: C[M,N] = A[M,K] @ B[K,N] (+bias) ----------
// BM=128, BN=64, BK=16, 256 threads, 8x4 register tile, double-buffered smem.
// Requires M%128==0, N%64==0, K%16==0 (true for all our shapes).
__global__ __launch_bounds__(256, 2)
void sgemm128x64(const float* __restrict__ A, const float* __restrict__ B,
                 const float* __restrict__ bias, float* __restrict__ C,
                 int N, int K)
{
    __shared__ float As[2][16][128];
    __shared__ float Bs[2][16][64];

    const int tid = threadIdx.x;
    const int tx  = tid & 15;      // column group (4 cols)
    const int ty  = tid >> 4;      // row group (8 rows)
    const int rowBase = blockIdx.y * 128;
    const int colBase = blockIdx.x * 64;

    // per-thread load coordinates (fixed across iterations)
    const int aM0 = (tid)        >> 2;          // A row for chunk 0
    const int aK0 = (tid & 3)    << 2;          // A k-offset for chunk 0
    const int aM1 = (tid + 256)  >> 2;          // A row for chunk 1
    const int aK1 = aK0;                        // same k pattern
    const int bK  = tid >> 4;                   // B k row
    const int bN  = (tid & 15) << 2;            // B col

    const float* Arow0 = A + (size_t)(rowBase + aM0) * K;
    const float* Arow1 = A + (size_t)(rowBase + aM1) * K;
    const float* Brow  = B + (size_t)bK * N + colBase + bN;

    float acc[8][4];
#pragma unroll
    for (int i = 0; i < 8; i++)
#pragma unroll
        for (int j = 0; j < 4; j++) acc[i][j] = 0.f;

    const int nIter = K >> 4;

    // prologue: load tile 0 into buffer 0
    {
        float4 a0 = *reinterpret_cast<const float4*>(&Arow0[aK0]);
        float4 a1 = *reinterpret_cast<const float4*>(&Arow1[aK1]);
        float4 b  = *reinterpret_cast<const float4*>(&Brow[0]);
        As[0][aK0 + 0][aM0] = a0.x; As[0][aK0 + 1][aM0] = a0.y;
        As[0][aK0 + 2][aM0] = a0.z; As[0][aK0 + 3][aM0] = a0.w;
        As[0][aK1 + 0][aM1] = a1.x; As[0][aK1 + 1][aM1] = a1.y;
        As[0][aK1 + 2][aM1] = a1.z; As[0][aK1 + 3][aM1] = a1.w;
        *reinterpret_cast<float4*>(&Bs[0][bK][bN]) = b;
    }
    __syncthreads();

    for (int it = 0; it < nIter; it++) {
        const int buf = it & 1;

        // issue next tile's global loads early (hide latency behind compute)
        float4 na0, na1, nb;
        const bool hasNext = (it + 1) < nIter;
        if (hasNext) {
            const int k0 = (it + 1) << 4;
            na0 = *reinterpret_cast<const float4*>(&Arow0[k0 + aK0]);
            na1 = *reinterpret_cast<const float4*>(&Arow1[k0 + aK1]);
            nb  = *reinterpret_cast<const float4*>(&Brow[(size_t)k0 * N]);
        }

#pragma unroll
        for (int k = 0; k < 16; k++) {
            float4 a0 = *reinterpret_cast<const float4*>(&As[buf][k][ty * 8]);
            float4 a1 = *reinterpret_cast<const float4*>(&As[buf][k][ty * 8 + 4]);
            float4 b  = *reinterpret_cast<const float4*>(&Bs[buf][k][tx * 4]);
            float av[8] = {a0.x, a0.y, a0.z, a0.w, a1.x, a1.y, a1.z, a1.w};
            float bv[4] = {b.x, b.y, b.z, b.w};
#pragma unroll
            for (int i = 0; i < 8; i++)
#pragma unroll
                for (int j = 0; j < 4; j++)
                    acc[i][j] = fmaf(av[i], bv[j], acc[i][j]);
        }

        if (hasNext) {
            const int nbuf = buf ^ 1;
            As[nbuf][aK0 + 0][aM0] = na0.x; As[nbuf][aK0 + 1][aM0] = na0.y;
            As[nbuf][aK0 + 2][aM0] = na0.z; As[nbuf][aK0 + 3][aM0] = na0.w;
            As[nbuf][aK1 + 0][aM1] = na1.x; As[nbuf][aK1 + 1][aM1] = na1.y;
            As[nbuf][aK1 + 2][aM1] = na1.z; As[nbuf][aK1 + 3][aM1] = na1.w;
            *reinterpret_cast<float4*>(&Bs[nbuf][bK][bN]) = nb;
        }
        __syncthreads();
    }

    float4 bb = make_float4(0.f, 0.f, 0.f, 0.f);
    if (bias) bb = *reinterpret_cast<const float4*>(&bias[colBase + tx * 4]);
#pragma unroll
    for (int i = 0; i < 8; i++) {
        int row = rowBase + ty * 8 + i;
        float4 o = make_float4(acc[i][0] + bb.x, acc[i][1] + bb.y,
                               acc[i][2] + bb.z, acc[i][3] + bb.w);
        *reinterpret_cast<float4*>(&C[(size_t)row * N + colBase + tx * 4]) = o;
    }
}

// ---------------- attention kernel ----------------
// One block per (window, head). 512 threads = 16 warps.
// Shared layout (floats):
#define SM_Q  0                         // 144*33
#define SM_K  4752                      // 144*33
#define SM_V  9504                      // 144*32
#define SM_S  14112                     // 144*144
#define SM_D1 34848                     // 144 ints
#define SM_D2 34992                     // 144 ints
#define SMEM_FLOATS 35136
#define ATTN_SMEM_BYTES (SMEM_FLOATS * 4)

__global__ __launch_bounds__(512, 1)
void attn_kernel(const float* __restrict__ qkv, const float* __restrict__ mask,
                 const float* __restrict__ bias_table, float* __restrict__ out)
{
    extern __shared__ float sm[];
    float* sq = sm + SM_Q;
    float* sk = sm + SM_K;
    float* sv = sm + SM_V;
    float* Ss = sm + SM_S;
    int*   d1s = (int*)(sm + SM_D1);
    int*   d2s = (int*)(sm + SM_D2);

    const int blk  = blockIdx.x;
    const int wn   = blk / HEADS;
    const int h    = blk - wn * HEADS;
    const int tid  = threadIdx.x;
    const int lane = tid & 31;
    const int wid  = tid >> 5;           // 0..15

    // window type: bn = mz*240 + mh*15 + mw ; wt = mz*16 + mh
    const int wt   = (wn / 240) * 16 + (wn / 15) % 16;
    const int wt6h = wt * HEADS + h;

    // load q, k, v tiles for this (window, head)
    for (int e = tid; e < P_TOK * DH; e += 512) {
        int p = e >> 5, d = e & 31;
        const float* base = qkv + ((size_t)wn * P_TOK + p) * NQKV + h * DH + d;
        sq[p * 33 + d] = base[0];
        sk[p * 33 + d] = base[DIMC];
        sv[p * 32 + d] = base[2 * DIMC];
    }
    // per-token position-index components:
    // idx(i,j) = d1[i] + d2[j] + 11  (into bias table rows)
    if (tid < P_TOK) {
        int z = tid / 72, rem = tid - z * 72;
        int hh = rem / 12, w = rem - hh * 12;
        d1s[tid] = z * 828 + hh * 23 + w;         // z_i*828 + h_i*23 + w_i
        d2s[tid] = z * 1656 + hh * 138 - w;       // 2z_j*828 + 6h_j*23 - w_j
    }
    __syncthreads();

    const float* maskw = mask + (size_t)wn * (P_TOK * P_TOK);

    // ---- S = scale * q @ k^T + bias + mask ; warp 'wid' owns rows wid+16t
#pragma unroll 1
    for (int t = 0; t < 4; t++) {
        const int i1 = wid + 32 * t;
        const int i2 = i1 + 16;
        float qa[32], qb[32];
#pragma unroll
        for (int d = 0; d < 32; d++) {
            qa[d] = sq[i1 * 33 + d];
            qb[d] = sq[i2 * 33 + d];
        }
        const int db1 = (d1s[i1] + 11) * BT_STRIDE + wt6h;
        const int db2 = (d1s[i2] + 11) * BT_STRIDE + wt6h;
#pragma unroll 1
        for (int j0 = 0; j0 < P_TOK; j0 += 32) {
            const int j = j0 + lane;
            if (j < P_TOK) {
                const int o2 = d2s[j] * BT_STRIDE;
                float bv1 = __ldg(&bias_table[db1 + o2]);
                float bv2 = __ldg(&bias_table[db2 + o2]);
                float m1  = maskw[i1 * P_TOK + j];
                float m2  = maskw[i2 * P_TOK + j];
                float a1 = 0.f, a2 = 0.f;
#pragma unroll
                for (int d = 0; d < 32; d++) {
                    float kv = sk[j * 33 + d];
                    a1 = fmaf(qa[d], kv, a1);
                    a2 = fmaf(qb[d], kv, a2);
                }
                Ss[i1 * P_TOK + j] = a1 * QK_SCALE + bv1 + m1;
                Ss[i2 * P_TOK + j] = a2 * QK_SCALE + bv2 + m2;
            }
        }
    }
    {   // leftover row i = wid + 128
        const int i1 = wid + 128;
        float qa[32];
#pragma unroll
        for (int d = 0; d < 32; d++) qa[d] = sq[i1 * 33 + d];
        const int db1 = (d1s[i1] + 11) * BT_STRIDE + wt6h;
#pragma unroll 1
        for (int j0 = 0; j0 < P_TOK; j0 += 32) {
            const int j = j0 + lane;
            if (j < P_TOK) {
                float bv1 = __ldg(&bias_table[db1 + d2s[j] * BT_STRIDE]);
                float m1  = maskw[i1 * P_TOK + j];
                float a1 = 0.f;
#pragma unroll
                for (int d = 0; d < 32; d++)
                    a1 = fmaf(qa[d], sk[j * 33 + d], a1);
                Ss[i1 * P_TOK + j] = a1 * QK_SCALE + bv1 + m1;
            }
        }
    }
    __syncwarp();

    // ---- softmax over rows owned by this warp (no cross-warp deps) ----
    for (int i = wid; i < P_TOK; i += 16) {
        float mx = -3.4e38f;
        for (int j = lane; j < P_TOK; j += 32)
            mx = fmaxf(mx, Ss[i * P_TOK + j]);
#pragma unroll
        for (int o = 16; o; o >>= 1)
            mx = fmaxf(mx, __shfl_xor_sync(0xffffffffu, mx, o));
        float sum = 0.f;
        for (int j = lane; j < P_TOK; j += 32) {
            float e = __expf(Ss[i * P_TOK + j] - mx);
            Ss[i * P_TOK + j] = e;
            sum += e;
        }
#pragma unroll
        for (int o = 16; o; o >>= 1)
            sum += __shfl_xor_sync(0xffffffffu, sum, o);
        float inv = 1.0f / sum;
        for (int j = lane; j < P_TOK; j += 32)
            Ss[i * P_TOK + j] *= inv;
    }
    __syncwarp();

    // ---- O = S @ V ; thread (wid, lane): rows wid+16r, col d = lane ----
    float acc[9];
#pragma unroll
    for (int r = 0; r < 9; r++) acc[r] = 0.f;
#pragma unroll 1
    for (int j = 0; j < P_TOK; j++) {
        float vv = sv[j * 32 + lane];
#pragma unroll
        for (int r = 0; r < 9; r++)
            acc[r] = fmaf(Ss[(wid + 16 * r) * P_TOK + j], vv, acc[r]);
    }
    float* outw = out + ((size_t)wn * P_TOK) * DIMC + h * DH + lane;
#pragma unroll
    for (int r = 0; r < 9; r++)
        outw[(size_t)(wid + 16 * r) * DIMC] = acc[r];
}

// ---------------- launch ----------------
extern "C" void kernel_launch(void* const* d_in, const int* in_sizes, int n_in,
                              void* d_out, int out_size)
{
    const float* x          = (const float*)d_in[0];   // (960*144, 192)
    const float* mask       = (const float*)d_in[1];   // (960, 144, 144)
    const float* w_qkv      = (const float*)d_in[2];   // (192, 576)
    const float* w_proj     = (const float*)d_in[3];   // (192, 192)
    const float* b_proj     = (const float*)d_in[4];   // (192,)
    const float* bias_table = (const float*)d_in[5];   // (3312, 64, 6)
    float* out = (float*)d_out;

    float* qkv = nullptr;
    float* att = nullptr;
    cudaGetSymbolAddress((void**)&qkv, g_qkv);
    cudaGetSymbolAddress((void**)&att, g_att);

    cudaFuncSetAttribute(attn_kernel,
                         cudaFuncAttributeMaxDynamicSharedMemorySize,
                         ATTN_SMEM_BYTES);

    // 1) QKV projection: (138240 x 192) @ (192 x 576)
    sgemm128x64<<<dim3(NQKV / 64, MROWS / 128), 256>>>(x, w_qkv, nullptr, qkv,
                                                       NQKV, DIMC);
    // 2) windowed attention with earth-position bias + mask
    attn_kernel<<<WN_WINDOWS * HEADS, 512, ATTN_SMEM_BYTES>>>(qkv, mask,
                                                              bias_table, att);
    // 3) output projection: (138240 x 192) @ (192 x 192) + bias
    sgemm128x64<<<dim3(DIMC / 64, MROWS / 128), 256>>>(att, w_proj, b_proj, out,
                                                       DIMC, DIMC);
}

// round 7
// speedup vs baseline: 1.2310x; 1.2310x over previous
#include <cuda_runtime.h>

// ---------------- problem constants ----------------
#define WN_WINDOWS 960
#define P_TOK      144
#define DIMC       192
#define HEADS      6
#define DH         32
#define NQKV       576          // 3*DIM
#define MROWS      138240       // 960*144
#define QK_SCALE   0.17677669529663687f   // 32^-0.5

// bias table geometry: (3312, 64, 6); stride over idx = 64*6 = 384
#define BT_STRIDE  384
#define WTH        384          // 64 window types * 6 heads
#define PP         (P_TOK * P_TOK)   // 20736

// ---------------- scratch (static device globals; no alloc allowed) -----
__device__ float g_qkv[(size_t)MROWS * NQKV];   // (BN*P, 3*DIM)
__device__ float g_att[(size_t)MROWS * DIMC];   // (BN*P, DIM)
__device__ float g_bias_pre[(size_t)WTH * PP];  // (wt*6+h, i, j) dense bias

// ---------------- fp32 GEMM: C[M,N] = A[M,K] @ B[K,N] (+bias) ----------
// BM=128, BN=64, BK=16, 256 threads, 8x4 register tile, double-buffered smem.
__global__ __launch_bounds__(256, 2)
void sgemm128x64(const float* __restrict__ A, const float* __restrict__ B,
                 const float* __restrict__ bias, float* __restrict__ C,
                 int N, int K)
{
    __shared__ float As[2][16][128];
    __shared__ float Bs[2][16][64];

    const int tid = threadIdx.x;
    const int tx  = tid & 15;
    const int ty  = tid >> 4;
    const int rowBase = blockIdx.y * 128;
    const int colBase = blockIdx.x * 64;

    const int aM0 = (tid)        >> 2;
    const int aK0 = (tid & 3)    << 2;
    const int aM1 = (tid + 256)  >> 2;
    const int aK1 = aK0;
    const int bK  = tid >> 4;
    const int bN  = (tid & 15) << 2;

    const float* Arow0 = A + (size_t)(rowBase + aM0) * K;
    const float* Arow1 = A + (size_t)(rowBase + aM1) * K;
    const float* Brow  = B + (size_t)bK * N + colBase + bN;

    float acc[8][4];
#pragma unroll
    for (int i = 0; i < 8; i++)
#pragma unroll
        for (int j = 0; j < 4; j++) acc[i][j] = 0.f;

    const int nIter = K >> 4;

    {
        float4 a0 = *reinterpret_cast<const float4*>(&Arow0[aK0]);
        float4 a1 = *reinterpret_cast<const float4*>(&Arow1[aK1]);
        float4 b  = *reinterpret_cast<const float4*>(&Brow[0]);
        As[0][aK0 + 0][aM0] = a0.x; As[0][aK0 + 1][aM0] = a0.y;
        As[0][aK0 + 2][aM0] = a0.z; As[0][aK0 + 3][aM0] = a0.w;
        As[0][aK1 + 0][aM1] = a1.x; As[0][aK1 + 1][aM1] = a1.y;
        As[0][aK1 + 2][aM1] = a1.z; As[0][aK1 + 3][aM1] = a1.w;
        *reinterpret_cast<float4*>(&Bs[0][bK][bN]) = b;
    }
    __syncthreads();

    for (int it = 0; it < nIter; it++) {
        const int buf = it & 1;
        float4 na0, na1, nb;
        const bool hasNext = (it + 1) < nIter;
        if (hasNext) {
            const int k0 = (it + 1) << 4;
            na0 = *reinterpret_cast<const float4*>(&Arow0[k0 + aK0]);
            na1 = *reinterpret_cast<const float4*>(&Arow1[k0 + aK1]);
            nb  = *reinterpret_cast<const float4*>(&Brow[(size_t)k0 * N]);
        }

#pragma unroll
        for (int k = 0; k < 16; k++) {
            float4 a0 = *reinterpret_cast<const float4*>(&As[buf][k][ty * 8]);
            float4 a1 = *reinterpret_cast<const float4*>(&As[buf][k][ty * 8 + 4]);
            float4 b  = *reinterpret_cast<const float4*>(&Bs[buf][k][tx * 4]);
            float av[8] = {a0.x, a0.y, a0.z, a0.w, a1.x, a1.y, a1.z, a1.w};
            float bv[4] = {b.x, b.y, b.z, b.w};
#pragma unroll
            for (int i = 0; i < 8; i++)
#pragma unroll
                for (int j = 0; j < 4; j++)
                    acc[i][j] = fmaf(av[i], bv[j], acc[i][j]);
        }

        if (hasNext) {
            const int nbuf = buf ^ 1;
            As[nbuf][aK0 + 0][aM0] = na0.x; As[nbuf][aK0 + 1][aM0] = na0.y;
            As[nbuf][aK0 + 2][aM0] = na0.z; As[nbuf][aK0 + 3][aM0] = na0.w;
            As[nbuf][aK1 + 0][aM1] = na1.x; As[nbuf][aK1 + 1][aM1] = na1.y;
            As[nbuf][aK1 + 2][aM1] = na1.z; As[nbuf][aK1 + 3][aM1] = na1.w;
            *reinterpret_cast<float4*>(&Bs[nbuf][bK][bN]) = nb;
        }
        __syncthreads();
    }

    float4 bb = make_float4(0.f, 0.f, 0.f, 0.f);
    if (bias) bb = *reinterpret_cast<const float4*>(&bias[colBase + tx * 4]);
#pragma unroll
    for (int i = 0; i < 8; i++) {
        int row = rowBase + ty * 8 + i;
        float4 o = make_float4(acc[i][0] + bb.x, acc[i][1] + bb.y,
                               acc[i][2] + bb.z, acc[i][3] + bb.w);
        *reinterpret_cast<float4*>(&C[(size_t)row * N + colBase + tx * 4]) = o;
    }
}

// ---------------- bias precompute: (3312,64,6) -> dense (384, 144, 144) --
// One block per (wt*6+h). Scattered reads (done ONCE per combo instead of
// 15x inside attention), coalesced writes.
__global__ __launch_bounds__(256)
void bias_pre_kernel(const float* __restrict__ bt, float* __restrict__ outp)
{
    __shared__ int d1s[P_TOK], d2s[P_TOK];
    const int wh = blockIdx.x;          // wt*6 + h
    const int tid = threadIdx.x;
    if (tid < P_TOK) {
        int z = tid / 72, rem = tid - z * 72;
        int hh = rem / 12, w = rem - hh * 12;
        d1s[tid] = z * 828 + hh * 23 + w;
        d2s[tid] = z * 1656 + hh * 138 - w;
    }
    __syncthreads();
    float* o = outp + (size_t)wh * PP;
    for (int e = tid; e < PP; e += 256) {
        int i = e / P_TOK, j = e - i * P_TOK;
        o[e] = __ldg(&bt[(size_t)(d1s[i] + d2s[j] + 11) * BT_STRIDE + wh]);
    }
}

// ---------------- attention kernel ----------------
// One block per (window, head). 512 threads = 16 warps.
// Shared layout (floats): padded k-rows (36) for LDS.128.
#define KPAD  36
#define SM_Q  0                         // 144*36 = 5184
#define SM_K  5184                      // 144*36 = 5184
#define SM_V  10368                     // 144*32 = 4608
#define SM_S  14976                     // 144*144 = 20736
#define SMEM_FLOATS 35712
#define ATTN_SMEM_BYTES (SMEM_FLOATS * 4)

__global__ __launch_bounds__(512, 1)
void attn_kernel(const float* __restrict__ qkv, const float* __restrict__ mask,
                 const float* __restrict__ bias_pre, float* __restrict__ out)
{
    extern __shared__ float sm[];
    float* sq = sm + SM_Q;
    float* sk = sm + SM_K;
    float* sv = sm + SM_V;
    float* Ss = sm + SM_S;

    const int blk  = blockIdx.x;
    const int wn   = blk / HEADS;
    const int h    = blk - wn * HEADS;
    const int tid  = threadIdx.x;
    const int lane = tid & 31;
    const int wid  = tid >> 5;           // 0..15

    // window type: wn = mz*240 + mh*15 + mw ; wt = mz*16 + mh
    const int wt   = (wn / 240) * 16 + (wn / 15) % 16;
    const float* bpre = bias_pre + (size_t)(wt * HEADS + h) * PP;

    // load q, k, v tiles for this (window, head)
    for (int e = tid; e < P_TOK * DH; e += 512) {
        int p = e >> 5, d = e & 31;
        const float* base = qkv + ((size_t)wn * P_TOK + p) * NQKV + h * DH + d;
        sq[p * KPAD + d] = base[0];
        sk[p * KPAD + d] = base[DIMC];
        sv[p * 32   + d] = base[2 * DIMC];
    }
    __syncthreads();

    const float* maskw = mask + (size_t)wn * PP;

    // ---- S = scale*q@k^T + bias + mask ; warp owns rows {wid+16t} ------
#pragma unroll 1
    for (int t = 0; t < 4; t++) {
        const int i1 = wid + 32 * t;
        const int i2 = i1 + 16;
        float4 qa[8], qb[8];
#pragma unroll
        for (int d4 = 0; d4 < 8; d4++) {
            qa[d4] = *reinterpret_cast<const float4*>(&sq[i1 * KPAD + d4 * 4]);
            qb[d4] = *reinterpret_cast<const float4*>(&sq[i2 * KPAD + d4 * 4]);
        }
#pragma unroll 1
        for (int j0 = 0; j0 < P_TOK; j0 += 32) {
            const int j = j0 + lane;
            if (j < P_TOK) {
                float bv1 = bpre[i1 * P_TOK + j];
                float bv2 = bpre[i2 * P_TOK + j];
                float m1  = maskw[i1 * P_TOK + j];
                float m2  = maskw[i2 * P_TOK + j];
                float a1 = 0.f, a2 = 0.f;
#pragma unroll
                for (int d4 = 0; d4 < 8; d4++) {
                    float4 kv = *reinterpret_cast<const float4*>(
                        &sk[j * KPAD + d4 * 4]);
                    a1 = fmaf(qa[d4].x, kv.x, a1); a2 = fmaf(qb[d4].x, kv.x, a2);
                    a1 = fmaf(qa[d4].y, kv.y, a1); a2 = fmaf(qb[d4].y, kv.y, a2);
                    a1 = fmaf(qa[d4].z, kv.z, a1); a2 = fmaf(qb[d4].z, kv.z, a2);
                    a1 = fmaf(qa[d4].w, kv.w, a1); a2 = fmaf(qb[d4].w, kv.w, a2);
                }
                Ss[i1 * P_TOK + j] = a1 * QK_SCALE + bv1 + m1;
                Ss[i2 * P_TOK + j] = a2 * QK_SCALE + bv2 + m2;
            }
        }
    }
    {   // leftover row i = wid + 128
        const int i1 = wid + 128;
        float4 qa[8];
#pragma unroll
        for (int d4 = 0; d4 < 8; d4++)
            qa[d4] = *reinterpret_cast<const float4*>(&sq[i1 * KPAD + d4 * 4]);
#pragma unroll 1
        for (int j0 = 0; j0 < P_TOK; j0 += 32) {
            const int j = j0 + lane;
            if (j < P_TOK) {
                float bv1 = bpre[i1 * P_TOK + j];
                float m1  = maskw[i1 * P_TOK + j];
                float a1 = 0.f;
#pragma unroll
                for (int d4 = 0; d4 < 8; d4++) {
                    float4 kv = *reinterpret_cast<const float4*>(
                        &sk[j * KPAD + d4 * 4]);
                    a1 = fmaf(qa[d4].x, kv.x, a1);
                    a1 = fmaf(qa[d4].y, kv.y, a1);
                    a1 = fmaf(qa[d4].z, kv.z, a1);
                    a1 = fmaf(qa[d4].w, kv.w, a1);
                }
                Ss[i1 * P_TOK + j] = a1 * QK_SCALE + bv1 + m1;
            }
        }
    }
    __syncwarp();

    // ---- softmax over rows owned by this warp -------------------------
    for (int i = wid; i < P_TOK; i += 16) {
        float mx = -3.4e38f;
        for (int j = lane; j < P_TOK; j += 32)
            mx = fmaxf(mx, Ss[i * P_TOK + j]);
#pragma unroll
        for (int o = 16; o; o >>= 1)
            mx = fmaxf(mx, __shfl_xor_sync(0xffffffffu, mx, o));
        float sum = 0.f;
        for (int j = lane; j < P_TOK; j += 32) {
            float e = __expf(Ss[i * P_TOK + j] - mx);
            Ss[i * P_TOK + j] = e;
            sum += e;
        }
#pragma unroll
        for (int o = 16; o; o >>= 1)
            sum += __shfl_xor_sync(0xffffffffu, sum, o);
        float inv = 1.0f / sum;
        for (int j = lane; j < P_TOK; j += 32)
            Ss[i * P_TOK + j] *= inv;
    }
    __syncwarp();

    // ---- O = S @ V ; thread (wid, lane): rows wid+16r, col d = lane ----
    float acc[9];
#pragma unroll
    for (int r = 0; r < 9; r++) acc[r] = 0.f;
#pragma unroll 1
    for (int j4 = 0; j4 < P_TOK / 4; j4++) {
        float4 s[9];
#pragma unroll
        for (int r = 0; r < 9; r++)
            s[r] = *reinterpret_cast<const float4*>(
                &Ss[(wid + 16 * r) * P_TOK + j4 * 4]);
        const float* svb = &sv[j4 * 4 * 32 + lane];
        float v0 = svb[0], v1 = svb[32], v2 = svb[64], v3 = svb[96];
#pragma unroll
        for (int r = 0; r < 9; r++) {
            acc[r] = fmaf(s[r].x, v0, acc[r]);
            acc[r] = fmaf(s[r].y, v1, acc[r]);
            acc[r] = fmaf(s[r].z, v2, acc[r]);
            acc[r] = fmaf(s[r].w, v3, acc[r]);
        }
    }
    float* outw = out + ((size_t)wn * P_TOK) * DIMC + h * DH + lane;
#pragma unroll
    for (int r = 0; r < 9; r++)
        outw[(size_t)(wid + 16 * r) * DIMC] = acc[r];
}

// ---------------- launch ----------------
extern "C" void kernel_launch(void* const* d_in, const int* in_sizes, int n_in,
                              void* d_out, int out_size)
{
    const float* x          = (const float*)d_in[0];
    const float* mask       = (const float*)d_in[1];
    const float* w_qkv      = (const float*)d_in[2];
    const float* w_proj     = (const float*)d_in[3];
    const float* b_proj     = (const float*)d_in[4];
    const float* bias_table = (const float*)d_in[5];
    float* out = (float*)d_out;

    float* qkv = nullptr;
    float* att = nullptr;
    float* bpre = nullptr;
    cudaGetSymbolAddress((void**)&qkv, g_qkv);
    cudaGetSymbolAddress((void**)&att, g_att);
    cudaGetSymbolAddress((void**)&bpre, g_bias_pre);

    cudaFuncSetAttribute(attn_kernel,
                         cudaFuncAttributeMaxDynamicSharedMemorySize,
                         ATTN_SMEM_BYTES);

    // 0) densify earth-position bias: (3312,64,6) -> (384,144,144)
    bias_pre_kernel<<<WTH, 256>>>(bias_table, bpre);
    // 1) QKV projection
    sgemm128x64<<<dim3(NQKV / 64, MROWS / 128), 256>>>(x, w_qkv, nullptr, qkv,
                                                       NQKV, DIMC);
    // 2) windowed attention
    attn_kernel<<<WN_WINDOWS * HEADS, 512, ATTN_SMEM_BYTES>>>(qkv, mask,
                                                              bpre, att);
    // 3) output projection
    sgemm128x64<<<dim3(DIMC / 64, MROWS / 128), 256>>>(att, w_proj, b_proj, out,
                                                       DIMC, DIMC);
}

// round 11
// speedup vs baseline: 1.7188x; 1.3962x over previous
#include <cuda_runtime.h>
#include <cuda_fp16.h>
#include <cstdint>

typedef unsigned int u32;

// ---------------- problem constants ----------------
#define WN_WINDOWS 960
#define P_TOK      144
#define DIMC       192
#define HEADS      6
#define DH         32
#define NQKV       576          // 3*DIM
#define MROWS      138240       // 960*144
#define QK_SCALE   0.17677669529663687f   // 32^-0.5

#define BT_STRIDE  384
#define WTH        384          // 64 window types * 6 heads
#define PP         (P_TOK * P_TOK)   // 20736

// ---------------- scratch (static device globals; no alloc allowed) -----
__device__ float  g_qkv[(size_t)MROWS * NQKV];     // (BN*P, 3*DIM) fp32
__device__ float  g_bias_pre[(size_t)WTH * PP];    // dense bias
__device__ __half g_x16[(size_t)MROWS * DIMC];     // x in fp16
__device__ __half g_att16[(size_t)MROWS * DIMC];   // attention out fp16
__device__ __half g_wqkv16[(size_t)DIMC * NQKV];
__device__ __half g_wproj16[(size_t)DIMC * DIMC];

// ---------------- fp32 -> fp16 conversion (vectorized) ------------------
__global__ void convert_f2h(const float* __restrict__ in,
                            __half* __restrict__ out, int n4)
{
    int i = blockIdx.x * blockDim.x + threadIdx.x;
    if (i < n4) {
        float4 v = reinterpret_cast<const float4*>(in)[i];
        __half2 h0 = __floats2half2_rn(v.x, v.y);
        __half2 h1 = __floats2half2_rn(v.z, v.w);
        reinterpret_cast<__half2*>(out)[i * 2]     = h0;
        reinterpret_cast<__half2*>(out)[i * 2 + 1] = h1;
    }
}

// ---------------- mma helpers -------------------------------------------
__device__ __forceinline__ void ldsm_x4(u32* r, u32 addr) {
    asm volatile("ldmatrix.sync.aligned.m8n8.x4.shared.b16 {%0,%1,%2,%3}, [%4];"
                 : "=r"(r[0]), "=r"(r[1]), "=r"(r[2]), "=r"(r[3]) : "r"(addr));
}
__device__ __forceinline__ void ldsm_x4_t(u32* r, u32 addr) {
    asm volatile("ldmatrix.sync.aligned.m8n8.x4.trans.shared.b16 {%0,%1,%2,%3}, [%4];"
                 : "=r"(r[0]), "=r"(r[1]), "=r"(r[2]), "=r"(r[3]) : "r"(addr));
}
__device__ __forceinline__ void mma16816(float* c, const u32* a, const u32* b) {
    asm volatile(
        "mma.sync.aligned.m16n8k16.row.col.f32.f16.f16.f32 "
        "{%0,%1,%2,%3}, {%4,%5,%6,%7}, {%8,%9}, {%0,%1,%2,%3};"
        : "+f"(c[0]), "+f"(c[1]), "+f"(c[2]), "+f"(c[3])
        : "r"(a[0]), "r"(a[1]), "r"(a[2]), "r"(a[3]), "r"(b[0]), "r"(b[1]));
}

// ---------------- fp16 GEMM: C[M,N] = A[M,K] @ B[K,N] (+bias), C fp32 ---
// BM=128, BN=64, BK=32, 256 threads = 8 warps (4x2 grid of 32x32 warptiles).
#define PADA 40   // As row stride (halfs)
#define PADB 72   // Bs row stride (halfs)

__global__ __launch_bounds__(256)
void hgemm128x64(const __half* __restrict__ A, const __half* __restrict__ B,
                 const float* __restrict__ bias, float* __restrict__ C,
                 int N, int K)
{
    __shared__ __half As[2][128 * PADA];
    __shared__ __half Bs[2][32 * PADB];

    const int tid  = threadIdx.x;
    const int lane = tid & 31;
    const int wid  = tid >> 5;
    const int warpM = (wid & 3) * 32;       // 0,32,64,96
    const int warpN = (wid >> 2) * 32;      // 0,32
    const int rowBase = blockIdx.y * 128;
    const int colBase = blockIdx.x * 64;

    // global load coords
    const int aRow   = tid >> 2;            // 0..63 (+64 second chunk)
    const int aChunk = (tid & 3) * 8;       // halfs
    const int bRow   = tid >> 3;            // 0..31
    const int bChunk = (tid & 7) * 8;

    const __half* Ag0 = A + (size_t)(rowBase + aRow) * K + aChunk;
    const __half* Ag1 = A + (size_t)(rowBase + aRow + 64) * K + aChunk;
    const __half* Bg  = B + (size_t)bRow * N + colBase + bChunk;

    float acc[2][4][4];
#pragma unroll
    for (int mt = 0; mt < 2; mt++)
#pragma unroll
        for (int nt = 0; nt < 4; nt++)
#pragma unroll
            for (int e = 0; e < 4; e++) acc[mt][nt][e] = 0.f;

    const int nTiles = K >> 5;   // K/32

    // prologue: tile 0
    {
        uint4 a0 = *reinterpret_cast<const uint4*>(Ag0);
        uint4 a1 = *reinterpret_cast<const uint4*>(Ag1);
        uint4 b0 = *reinterpret_cast<const uint4*>(Bg);
        *reinterpret_cast<uint4*>(&As[0][aRow * PADA + aChunk])        = a0;
        *reinterpret_cast<uint4*>(&As[0][(aRow + 64) * PADA + aChunk]) = a1;
        *reinterpret_cast<uint4*>(&Bs[0][bRow * PADB + bChunk])        = b0;
    }
    __syncthreads();

    for (int kt = 0; kt < nTiles; kt++) {
        const int buf = kt & 1;
        const bool hasNext = (kt + 1) < nTiles;
        uint4 na0, na1, nb0;
        if (hasNext) {
            const int k0 = (kt + 1) << 5;
            na0 = *reinterpret_cast<const uint4*>(Ag0 + k0);
            na1 = *reinterpret_cast<const uint4*>(Ag1 + k0);
            nb0 = *reinterpret_cast<const uint4*>(Bg + (size_t)k0 * N);
        }

        const u32 aBase = (u32)__cvta_generic_to_shared(&As[buf][0]);
        const u32 bBase = (u32)__cvta_generic_to_shared(&Bs[buf][0]);
        const int l15 = lane & 15;
        const int l16 = (lane >> 4) * 8;

#pragma unroll
        for (int ks = 0; ks < 32; ks += 16) {
            u32 af[2][4], bf[2][4];
#pragma unroll
            for (int mt = 0; mt < 2; mt++)
                ldsm_x4(af[mt], aBase +
                        (u32)((warpM + mt * 16 + l15) * PADA + ks + l16) * 2u);
#pragma unroll
            for (int ng = 0; ng < 2; ng++)
                ldsm_x4_t(bf[ng], bBase +
                          (u32)((ks + l15) * PADB + warpN + ng * 16 + l16) * 2u);
#pragma unroll
            for (int mt = 0; mt < 2; mt++)
#pragma unroll
                for (int nt = 0; nt < 4; nt++)
                    mma16816(acc[mt][nt], af[mt], &bf[nt >> 1][(nt & 1) * 2]);
        }

        if (hasNext) {
            const int nbuf = buf ^ 1;
            *reinterpret_cast<uint4*>(&As[nbuf][aRow * PADA + aChunk])        = na0;
            *reinterpret_cast<uint4*>(&As[nbuf][(aRow + 64) * PADA + aChunk]) = na1;
            *reinterpret_cast<uint4*>(&Bs[nbuf][bRow * PADB + bChunk])        = nb0;
        }
        __syncthreads();
    }

    // epilogue: c0,c1 -> (row, col..col+1); c2,c3 -> (row+8, ...)
    const int rBase = rowBase + warpM + (lane >> 2);
    const int cBase = colBase + warpN + (lane & 3) * 2;
#pragma unroll
    for (int mt = 0; mt < 2; mt++) {
#pragma unroll
        for (int nt = 0; nt < 4; nt++) {
            int col = cBase + nt * 8;
            float b0 = 0.f, b1 = 0.f;
            if (bias) { b0 = bias[col]; b1 = bias[col + 1]; }
            int r0 = rBase + mt * 16;
            float2 v0 = make_float2(acc[mt][nt][0] + b0, acc[mt][nt][1] + b1);
            float2 v1 = make_float2(acc[mt][nt][2] + b0, acc[mt][nt][3] + b1);
            *reinterpret_cast<float2*>(&C[(size_t)r0 * N + col])       = v0;
            *reinterpret_cast<float2*>(&C[(size_t)(r0 + 8) * N + col]) = v1;
        }
    }
}

// ---------------- bias precompute: (3312,64,6) -> dense (384,144,144) ---
__global__ __launch_bounds__(256)
void bias_pre_kernel(const float* __restrict__ bt, float* __restrict__ outp)
{
    __shared__ int d1s[P_TOK], d2s[P_TOK];
    const int wh = blockIdx.x;
    const int tid = threadIdx.x;
    if (tid < P_TOK) {
        int z = tid / 72, rem = tid - z * 72;
        int hh = rem / 12, w = rem - hh * 12;
        d1s[tid] = z * 828 + hh * 23 + w;
        d2s[tid] = z * 1656 + hh * 138 - w;
    }
    __syncthreads();
    float* o = outp + (size_t)wh * PP;
    for (int e = tid; e < PP; e += 256) {
        int i = e / P_TOK, j = e - i * P_TOK;
        o[e] = __ldg(&bt[(size_t)(d1s[i] + d2s[j] + 11) * BT_STRIDE + wh]);
    }
}

// ---------------- attention kernel (fp32 math, fp16 output) -------------
#define KPAD  36
#define SM_Q  0
#define SM_K  5184
#define SM_V  10368
#define SM_S  14976
#define SMEM_FLOATS 35712
#define ATTN_SMEM_BYTES (SMEM_FLOATS * 4)

__global__ __launch_bounds__(512, 1)
void attn_kernel(const float* __restrict__ qkv, const float* __restrict__ mask,
                 const float* __restrict__ bias_pre, __half* __restrict__ out)
{
    extern __shared__ float sm[];
    float* sq = sm + SM_Q;
    float* sk = sm + SM_K;
    float* sv = sm + SM_V;
    float* Ss = sm + SM_S;

    const int blk  = blockIdx.x;
    const int wn   = blk / HEADS;
    const int h    = blk - wn * HEADS;
    const int tid  = threadIdx.x;
    const int lane = tid & 31;
    const int wid  = tid >> 5;

    const int wt   = (wn / 240) * 16 + (wn / 15) % 16;
    const float* bpre = bias_pre + (size_t)(wt * HEADS + h) * PP;

    for (int e = tid; e < P_TOK * DH; e += 512) {
        int p = e >> 5, d = e & 31;
        const float* base = qkv + ((size_t)wn * P_TOK + p) * NQKV + h * DH + d;
        sq[p * KPAD + d] = base[0];
        sk[p * KPAD + d] = base[DIMC];
        sv[p * 32   + d] = base[2 * DIMC];
    }
    __syncthreads();

    const float* maskw = mask + (size_t)wn * PP;

#pragma unroll 1
    for (int t = 0; t < 4; t++) {
        const int i1 = wid + 32 * t;
        const int i2 = i1 + 16;
        float4 qa[8], qb[8];
#pragma unroll
        for (int d4 = 0; d4 < 8; d4++) {
            qa[d4] = *reinterpret_cast<const float4*>(&sq[i1 * KPAD + d4 * 4]);
            qb[d4] = *reinterpret_cast<const float4*>(&sq[i2 * KPAD + d4 * 4]);
        }
#pragma unroll 1
        for (int j0 = 0; j0 < P_TOK; j0 += 32) {
            const int j = j0 + lane;
            if (j < P_TOK) {
                float bv1 = bpre[i1 * P_TOK + j];
                float bv2 = bpre[i2 * P_TOK + j];
                float m1  = maskw[i1 * P_TOK + j];
                float m2  = maskw[i2 * P_TOK + j];
                float a1 = 0.f, a2 = 0.f;
#pragma unroll
                for (int d4 = 0; d4 < 8; d4++) {
                    float4 kv = *reinterpret_cast<const float4*>(
                        &sk[j * KPAD + d4 * 4]);
                    a1 = fmaf(qa[d4].x, kv.x, a1); a2 = fmaf(qb[d4].x, kv.x, a2);
                    a1 = fmaf(qa[d4].y, kv.y, a1); a2 = fmaf(qb[d4].y, kv.y, a2);
                    a1 = fmaf(qa[d4].z, kv.z, a1); a2 = fmaf(qb[d4].z, kv.z, a2);
                    a1 = fmaf(qa[d4].w, kv.w, a1); a2 = fmaf(qb[d4].w, kv.w, a2);
                }
                Ss[i1 * P_TOK + j] = a1 * QK_SCALE + bv1 + m1;
                Ss[i2 * P_TOK + j] = a2 * QK_SCALE + bv2 + m2;
            }
        }
    }
    {
        const int i1 = wid + 128;
        float4 qa[8];
#pragma unroll
        for (int d4 = 0; d4 < 8; d4++)
            qa[d4] = *reinterpret_cast<const float4*>(&sq[i1 * KPAD + d4 * 4]);
#pragma unroll 1
        for (int j0 = 0; j0 < P_TOK; j0 += 32) {
            const int j = j0 + lane;
            if (j < P_TOK) {
                float bv1 = bpre[i1 * P_TOK + j];
                float m1  = maskw[i1 * P_TOK + j];
                float a1 = 0.f;
#pragma unroll
                for (int d4 = 0; d4 < 8; d4++) {
                    float4 kv = *reinterpret_cast<const float4*>(
                        &sk[j * KPAD + d4 * 4]);
                    a1 = fmaf(qa[d4].x, kv.x, a1);
                    a1 = fmaf(qa[d4].y, kv.y, a1);
                    a1 = fmaf(qa[d4].z, kv.z, a1);
                    a1 = fmaf(qa[d4].w, kv.w, a1);
                }
                Ss[i1 * P_TOK + j] = a1 * QK_SCALE + bv1 + m1;
            }
        }
    }
    __syncwarp();

    for (int i = wid; i < P_TOK; i += 16) {
        float mx = -3.4e38f;
        for (int j = lane; j < P_TOK; j += 32)
            mx = fmaxf(mx, Ss[i * P_TOK + j]);
#pragma unroll
        for (int o = 16; o; o >>= 1)
            mx = fmaxf(mx, __shfl_xor_sync(0xffffffffu, mx, o));
        float sum = 0.f;
        for (int j = lane; j < P_TOK; j += 32) {
            float e = __expf(Ss[i * P_TOK + j] - mx);
            Ss[i * P_TOK + j] = e;
            sum += e;
        }
#pragma unroll
        for (int o = 16; o; o >>= 1)
            sum += __shfl_xor_sync(0xffffffffu, sum, o);
        float inv = 1.0f / sum;
        for (int j = lane; j < P_TOK; j += 32)
            Ss[i * P_TOK + j] *= inv;
    }
    __syncwarp();

    float acc[9];
#pragma unroll
    for (int r = 0; r < 9; r++) acc[r] = 0.f;
#pragma unroll 1
    for (int j4 = 0; j4 < P_TOK / 4; j4++) {
        float4 s[9];
#pragma unroll
        for (int r = 0; r < 9; r++)
            s[r] = *reinterpret_cast<const float4*>(
                &Ss[(wid + 16 * r) * P_TOK + j4 * 4]);
        const float* svb = &sv[j4 * 4 * 32 + lane];
        float v0 = svb[0], v1 = svb[32], v2 = svb[64], v3 = svb[96];
#pragma unroll
        for (int r = 0; r < 9; r++) {
            acc[r] = fmaf(s[r].x, v0, acc[r]);
            acc[r] = fmaf(s[r].y, v1, acc[r]);
            acc[r] = fmaf(s[r].z, v2, acc[r]);
            acc[r] = fmaf(s[r].w, v3, acc[r]);
        }
    }
    __half* outw = out + ((size_t)wn * P_TOK) * DIMC + h * DH + lane;
#pragma unroll
    for (int r = 0; r < 9; r++)
        outw[(size_t)(wid + 16 * r) * DIMC] = __float2half_rn(acc[r]);
}

// ---------------- launch ----------------
extern "C" void kernel_launch(void* const* d_in, const int* in_sizes, int n_in,
                              void* d_out, int out_size)
{
    const float* x          = (const float*)d_in[0];
    const float* mask       = (const float*)d_in[1];
    const float* w_qkv      = (const float*)d_in[2];
    const float* w_proj     = (const float*)d_in[3];
    const float* b_proj     = (const float*)d_in[4];
    const float* bias_table = (const float*)d_in[5];
    float* out = (float*)d_out;

    float*  qkv   = 0;
    float*  bpre  = 0;
    __half* x16   = 0;
    __half* att16 = 0;
    __half* wq16  = 0;
    __half* wp16  = 0;
    cudaGetSymbolAddress((void**)&qkv,   g_qkv);
    cudaGetSymbolAddress((void**)&bpre,  g_bias_pre);
    cudaGetSymbolAddress((void**)&x16,   g_x16);
    cudaGetSymbolAddress((void**)&att16, g_att16);
    cudaGetSymbolAddress((void**)&wq16,  g_wqkv16);
    cudaGetSymbolAddress((void**)&wp16,  g_wproj16);

    cudaFuncSetAttribute(attn_kernel,
                         cudaFuncAttributeMaxDynamicSharedMemorySize,
                         ATTN_SMEM_BYTES);

    // 0) conversions + dense bias
    int n4 = (MROWS * DIMC) / 4;
    convert_f2h<<<(n4 + 255) / 256, 256>>>(x, x16, n4);
    int w4 = (DIMC * NQKV) / 4;
    convert_f2h<<<(w4 + 255) / 256, 256>>>(w_qkv, wq16, w4);
    int p4 = (DIMC * DIMC) / 4;
    convert_f2h<<<(p4 + 255) / 256, 256>>>(w_proj, wp16, p4);
    bias_pre_kernel<<<WTH, 256>>>(bias_table, bpre);

    // 1) QKV projection (fp16 tensor-core, fp32 out)
    hgemm128x64<<<dim3(NQKV / 64, MROWS / 128), 256>>>(x16, wq16, (const float*)0,
                                                       qkv, NQKV, DIMC);
    // 2) windowed attention (fp32 math, writes fp16)
    attn_kernel<<<WN_WINDOWS * HEADS, 512, ATTN_SMEM_BYTES>>>(qkv, mask,
                                                              bpre, att16);
    // 3) output projection (fp16 tensor-core, fp32 out + bias)
    hgemm128x64<<<dim3(DIMC / 64, MROWS / 128), 256>>>(att16, wp16, b_proj,
                                                       out, DIMC, DIMC);
}

// round 16
// speedup vs baseline: 3.0466x; 1.7725x over previous
#include <cuda_runtime.h>
#include <cuda_fp16.h>
#include <cstdint>

typedef unsigned int u32;

// ---------------- problem constants ----------------
#define WN_WINDOWS 960
#define P_TOK      144
#define DIMC       192
#define HEADS      6
#define DH         32
#define NQKV       576          // 3*DIM
#define MROWS      138240       // 960*144
#define QK_SCALE   0.17677669529663687f   // 32^-0.5

#define BT_STRIDE  384
#define WTH        384          // 64 window types * 6 heads
#define PP         (P_TOK * P_TOK)   // 20736

// ---------------- scratch (static device globals; no alloc allowed) -----
__device__ __half g_qkv16[(size_t)MROWS * NQKV];   // (BN*P, 3*DIM) fp16
__device__ float  g_bias_pre[(size_t)WTH * PP];    // dense bias
__device__ __half g_x16[(size_t)MROWS * DIMC];     // x in fp16
__device__ __half g_att16[(size_t)MROWS * DIMC];   // attention out fp16
__device__ __half g_wqkv16[(size_t)DIMC * NQKV];
__device__ __half g_wproj16[(size_t)DIMC * DIMC];

// ---------------- fp32 -> fp16 conversion (vectorized) ------------------
__global__ void convert_f2h(const float* __restrict__ in,
                            __half* __restrict__ out, int n4)
{
    int i = blockIdx.x * blockDim.x + threadIdx.x;
    if (i < n4) {
        float4 v = reinterpret_cast<const float4*>(in)[i];
        reinterpret_cast<__half2*>(out)[i * 2]     = __floats2half2_rn(v.x, v.y);
        reinterpret_cast<__half2*>(out)[i * 2 + 1] = __floats2half2_rn(v.z, v.w);
    }
}

// ---------------- mma helpers (fragment scheme verified in R11) ---------
__device__ __forceinline__ void ldsm_x4(u32* r, u32 addr) {
    asm volatile("ldmatrix.sync.aligned.m8n8.x4.shared.b16 {%0,%1,%2,%3}, [%4];"
                 : "=r"(r[0]), "=r"(r[1]), "=r"(r[2]), "=r"(r[3]) : "r"(addr));
}
__device__ __forceinline__ void ldsm_x4_t(u32* r, u32 addr) {
    asm volatile("ldmatrix.sync.aligned.m8n8.x4.trans.shared.b16 {%0,%1,%2,%3}, [%4];"
                 : "=r"(r[0]), "=r"(r[1]), "=r"(r[2]), "=r"(r[3]) : "r"(addr));
}
__device__ __forceinline__ void mma16816(float* c, const u32* a, const u32* b) {
    asm volatile(
        "mma.sync.aligned.m16n8k16.row.col.f32.f16.f16.f32 "
        "{%0,%1,%2,%3}, {%4,%5,%6,%7}, {%8,%9}, {%0,%1,%2,%3};"
        : "+f"(c[0]), "+f"(c[1]), "+f"(c[2]), "+f"(c[3])
        : "r"(a[0]), "r"(a[1]), "r"(a[2]), "r"(a[3]), "r"(b[0]), "r"(b[1]));
}

// ---------------- fp16 GEMM: C[M,N] = A[M,K] @ B[K,N] (+bias) ----------
// BM=128, BN=64, BK=32, 256 threads = 8 warps. HOUT: store fp16 else fp32.
#define PADA 40   // As row stride (halfs)
#define PADB 72   // Bs row stride (halfs)

template <bool HOUT>
__global__ __launch_bounds__(256)
void hgemm128x64(const __half* __restrict__ A, const __half* __restrict__ B,
                 const float* __restrict__ bias, void* __restrict__ Cv,
                 int N, int K)
{
    __shared__ __half As[2][128 * PADA];
    __shared__ __half Bs[2][32 * PADB];

    const int tid  = threadIdx.x;
    const int lane = tid & 31;
    const int wid  = tid >> 5;
    const int warpM = (wid & 3) * 32;
    const int warpN = (wid >> 2) * 32;
    const int rowBase = blockIdx.y * 128;
    const int colBase = blockIdx.x * 64;

    const int aRow   = tid >> 2;
    const int aChunk = (tid & 3) * 8;
    const int bRow   = tid >> 3;
    const int bChunk = (tid & 7) * 8;

    const __half* Ag0 = A + (size_t)(rowBase + aRow) * K + aChunk;
    const __half* Ag1 = A + (size_t)(rowBase + aRow + 64) * K + aChunk;
    const __half* Bg  = B + (size_t)bRow * N + colBase + bChunk;

    float acc[2][4][4];
#pragma unroll
    for (int mt = 0; mt < 2; mt++)
#pragma unroll
        for (int nt = 0; nt < 4; nt++)
#pragma unroll
            for (int e = 0; e < 4; e++) acc[mt][nt][e] = 0.f;

    const int nTiles = K >> 5;

    {
        uint4 a0 = *reinterpret_cast<const uint4*>(Ag0);
        uint4 a1 = *reinterpret_cast<const uint4*>(Ag1);
        uint4 b0 = *reinterpret_cast<const uint4*>(Bg);
        *reinterpret_cast<uint4*>(&As[0][aRow * PADA + aChunk])        = a0;
        *reinterpret_cast<uint4*>(&As[0][(aRow + 64) * PADA + aChunk]) = a1;
        *reinterpret_cast<uint4*>(&Bs[0][bRow * PADB + bChunk])        = b0;
    }
    __syncthreads();

    for (int kt = 0; kt < nTiles; kt++) {
        const int buf = kt & 1;
        const bool hasNext = (kt + 1) < nTiles;
        uint4 na0, na1, nb0;
        if (hasNext) {
            const int k0 = (kt + 1) << 5;
            na0 = *reinterpret_cast<const uint4*>(Ag0 + k0);
            na1 = *reinterpret_cast<const uint4*>(Ag1 + k0);
            nb0 = *reinterpret_cast<const uint4*>(Bg + (size_t)k0 * N);
        }

        const u32 aBase = (u32)__cvta_generic_to_shared(&As[buf][0]);
        const u32 bBase = (u32)__cvta_generic_to_shared(&Bs[buf][0]);
        const int l15 = lane & 15;
        const int l16 = (lane >> 4) * 8;

#pragma unroll
        for (int ks = 0; ks < 32; ks += 16) {
            u32 af[2][4], bf[2][4];
#pragma unroll
            for (int mt = 0; mt < 2; mt++)
                ldsm_x4(af[mt], aBase +
                        (u32)((warpM + mt * 16 + l15) * PADA + ks + l16) * 2u);
#pragma unroll
            for (int ng = 0; ng < 2; ng++)
                ldsm_x4_t(bf[ng], bBase +
                          (u32)((ks + l15) * PADB + warpN + ng * 16 + l16) * 2u);
#pragma unroll
            for (int mt = 0; mt < 2; mt++)
#pragma unroll
                for (int nt = 0; nt < 4; nt++)
                    mma16816(acc[mt][nt], af[mt], &bf[nt >> 1][(nt & 1) * 2]);
        }

        if (hasNext) {
            const int nbuf = buf ^ 1;
            *reinterpret_cast<uint4*>(&As[nbuf][aRow * PADA + aChunk])        = na0;
            *reinterpret_cast<uint4*>(&As[nbuf][(aRow + 64) * PADA + aChunk]) = na1;
            *reinterpret_cast<uint4*>(&Bs[nbuf][bRow * PADB + bChunk])        = nb0;
        }
        __syncthreads();
    }

    const int rBase = rowBase + warpM + (lane >> 2);
    const int cBase = colBase + warpN + (lane & 3) * 2;
#pragma unroll
    for (int mt = 0; mt < 2; mt++) {
#pragma unroll
        for (int nt = 0; nt < 4; nt++) {
            int col = cBase + nt * 8;
            float b0 = 0.f, b1 = 0.f;
            if (bias) { b0 = bias[col]; b1 = bias[col + 1]; }
            int r0 = rBase + mt * 16;
            if (HOUT) {
                __half* C16 = (__half*)Cv;
                *reinterpret_cast<__half2*>(&C16[(size_t)r0 * N + col]) =
                    __floats2half2_rn(acc[mt][nt][0] + b0, acc[mt][nt][1] + b1);
                *reinterpret_cast<__half2*>(&C16[(size_t)(r0 + 8) * N + col]) =
                    __floats2half2_rn(acc[mt][nt][2] + b0, acc[mt][nt][3] + b1);
            } else {
                float* C = (float*)Cv;
                *reinterpret_cast<float2*>(&C[(size_t)r0 * N + col]) =
                    make_float2(acc[mt][nt][0] + b0, acc[mt][nt][1] + b1);
                *reinterpret_cast<float2*>(&C[(size_t)(r0 + 8) * N + col]) =
                    make_float2(acc[mt][nt][2] + b0, acc[mt][nt][3] + b1);
            }
        }
    }
}

// ---------------- bias precompute: (3312,64,6) -> dense (384,144,144) ---
__global__ __launch_bounds__(256)
void bias_pre_kernel(const float* __restrict__ bt, float* __restrict__ outp)
{
    __shared__ int d1s[P_TOK], d2s[P_TOK];
    const int wh = blockIdx.x;
    const int tid = threadIdx.x;
    if (tid < P_TOK) {
        int z = tid / 72, rem = tid - z * 72;
        int hh = rem / 12, w = rem - hh * 12;
        d1s[tid] = z * 828 + hh * 23 + w;
        d2s[tid] = z * 1656 + hh * 138 - w;
    }
    __syncthreads();
    float* o = outp + (size_t)wh * PP;
    for (int e = tid; e < PP; e += 256) {
        int i = e / P_TOK, j = e - i * P_TOK;
        o[e] = __ldg(&bt[(size_t)(d1s[i] + d2s[j] + 11) * BT_STRIDE + wh]);
    }
}

// ---------------- attention kernel: full tensor-core --------------------
// One block per (window, head). 512 threads = 16 warps.
#define QVPAD   40                      // q/k/v row stride in halfs
#define SPAD    152                     // S16 row stride in halfs
#define SMQ     0                       // 144*40 halfs = 11520 B
#define SMK     11520
#define SMV     23040
#define SMS32   34560                   // 144*144 floats = 82944 B
#define SMS16   117504                  // 144*152 halfs  = 43776 B
#define SMSINV  161280                  // 144 floats
#define AT_SMEM (161280 + 144 * 4)

__global__ __launch_bounds__(512, 1)
void attn_mma(const __half* __restrict__ qkv, const float* __restrict__ mask,
              const float* __restrict__ bias_pre, __half* __restrict__ out)
{
    extern __shared__ char smx[];
    __half* sq   = (__half*)(smx + SMQ);
    __half* sk   = (__half*)(smx + SMK);
    __half* sv   = (__half*)(smx + SMV);
    float*  S32  = (float*)(smx + SMS32);
    __half* S16  = (__half*)(smx + SMS16);
    float*  sinv = (float*)(smx + SMSINV);

    const int blk  = blockIdx.x;
    const int wn   = blk / HEADS;
    const int h    = blk - wn * HEADS;
    const int tid  = threadIdx.x;
    const int lane = tid & 31;
    const int wid  = tid >> 5;            // 0..15

    const int wt = (wn / 240) * 16 + (wn / 15) % 16;
    const float* bpre  = bias_pre + (size_t)(wt * HEADS + h) * PP;
    const float* maskw = mask + (size_t)wn * PP;

    // ---- load q,k,v (fp16): 144 rows x 32 halfs = 4 uint4 chunks/row ---
    for (int e = tid; e < P_TOK * 4; e += 512) {
        int p = e >> 2, c = (e & 3) * 8;
        const __half* base = qkv + ((size_t)wn * P_TOK + p) * NQKV + h * DH + c;
        uint4 vq = *reinterpret_cast<const uint4*>(base);
        uint4 vk = *reinterpret_cast<const uint4*>(base + DIMC);
        uint4 vv = *reinterpret_cast<const uint4*>(base + 2 * DIMC);
        *reinterpret_cast<uint4*>(&sq[p * QVPAD + c]) = vq;
        *reinterpret_cast<uint4*>(&sk[p * QVPAD + c]) = vk;
        *reinterpret_cast<uint4*>(&sv[p * QVPAD + c]) = vv;
    }
    __syncthreads();

    const u32 sqB = (u32)__cvta_generic_to_shared(sq);
    const u32 skB = (u32)__cvta_generic_to_shared(sk);
    const u32 svB = (u32)__cvta_generic_to_shared(sv);
    const u32 s16B = (u32)__cvta_generic_to_shared(S16);
    const int l15 = lane & 15;
    const int l16 = (lane >> 4) * 8;

    // ---- S = scale*q@k^T + bias + mask : 81 tiles of m16n16, k=32 ------
    // sk is [n][k] row-major => B fragment via NON-trans ldsm (A-style
    // addressing); x4 tile order gives n-octet pairs (r0,r2) and (r1,r3).
    for (int t = wid; t < 81; t += 16) {
        const int mt = (t / 9) * 16;
        const int nt = (t % 9) * 16;
        float acc[2][4];
#pragma unroll
        for (int g = 0; g < 2; g++)
#pragma unroll
            for (int e = 0; e < 4; e++) acc[g][e] = 0.f;

#pragma unroll
        for (int ks = 0; ks < 32; ks += 16) {
            u32 af[4], bf[4];
            ldsm_x4(af, sqB + (u32)((mt + l15) * QVPAD + ks + l16) * 2u);
            ldsm_x4(bf, skB + (u32)((nt + l15) * QVPAD + ks + l16) * 2u);
            u32 blo[2] = { bf[0], bf[2] };   // n 0-7 : k lo, k hi
            u32 bhi[2] = { bf[1], bf[3] };   // n 8-15: k lo, k hi
            mma16816(acc[0], af, blo);
            mma16816(acc[1], af, bhi);
        }
        const int r0 = mt + (lane >> 2);
        const int c0 = nt + (lane & 3) * 2;
#pragma unroll
        for (int g = 0; g < 2; g++) {
            const int c = c0 + g * 8;
            float2 b0 = *reinterpret_cast<const float2*>(&bpre[r0 * P_TOK + c]);
            float2 m0 = *reinterpret_cast<const float2*>(&maskw[r0 * P_TOK + c]);
            float2 b1 = *reinterpret_cast<const float2*>(&bpre[(r0 + 8) * P_TOK + c]);
            float2 m1 = *reinterpret_cast<const float2*>(&maskw[(r0 + 8) * P_TOK + c]);
            S32[r0 * P_TOK + c]           = acc[g][0] * QK_SCALE + b0.x + m0.x;
            S32[r0 * P_TOK + c + 1]       = acc[g][1] * QK_SCALE + b0.y + m0.y;
            S32[(r0 + 8) * P_TOK + c]     = acc[g][2] * QK_SCALE + b1.x + m1.x;
            S32[(r0 + 8) * P_TOK + c + 1] = acc[g][3] * QK_SCALE + b1.y + m1.y;
        }
    }
    __syncthreads();

    // ---- softmax: store UNNORMALIZED exp to S16; 1/sum kept per row ----
    for (int i = wid; i < P_TOK; i += 16) {
        float mx = -3.4e38f;
        for (int j = lane; j < P_TOK; j += 32)
            mx = fmaxf(mx, S32[i * P_TOK + j]);
#pragma unroll
        for (int o = 16; o; o >>= 1)
            mx = fmaxf(mx, __shfl_xor_sync(0xffffffffu, mx, o));
        float sum = 0.f;
        for (int j = lane; j < P_TOK; j += 32) {
            float e = __expf(S32[i * P_TOK + j] - mx);
            sum += e;
            S16[i * SPAD + j] = __float2half_rn(e);
        }
#pragma unroll
        for (int o = 16; o; o >>= 1)
            sum += __shfl_xor_sync(0xffffffffu, sum, o);
        if (lane == 0) sinv[i] = 1.0f / sum;
    }
    __syncthreads();

    // ---- O = (E @ V) * sinv : 18 tiles of m16n16, k=144 ----------------
    // sv is [k][n] row-major => trans ldsm, hgemm-verified pairing.
    for (int t = wid; t < 18; t += 16) {
        const int mt = (t >> 1) * 16;
        const int nt = (t & 1) * 16;
        float acc[2][4];
#pragma unroll
        for (int g = 0; g < 2; g++)
#pragma unroll
            for (int e = 0; e < 4; e++) acc[g][e] = 0.f;

#pragma unroll 1
        for (int ks = 0; ks < P_TOK; ks += 16) {
            u32 af[4], bf[4];
            ldsm_x4(af, s16B + (u32)((mt + l15) * SPAD + ks + l16) * 2u);
            ldsm_x4_t(bf, svB + (u32)((ks + l15) * QVPAD + nt + l16) * 2u);
            mma16816(acc[0], af, &bf[0]);
            mma16816(acc[1], af, &bf[2]);
        }
        const int r0 = mt + (lane >> 2);
        const int c0 = nt + (lane & 3) * 2;
        const float s0 = sinv[r0];
        const float s1 = sinv[r0 + 8];
        __half* o0 = out + ((size_t)wn * P_TOK + r0) * DIMC + h * DH;
        __half* o1 = out + ((size_t)wn * P_TOK + r0 + 8) * DIMC + h * DH;
#pragma unroll
        for (int g = 0; g < 2; g++) {
            const int c = c0 + g * 8;
            *reinterpret_cast<__half2*>(&o0[c]) =
                __floats2half2_rn(acc[g][0] * s0, acc[g][1] * s0);
            *reinterpret_cast<__half2*>(&o1[c]) =
                __floats2half2_rn(acc[g][2] * s1, acc[g][3] * s1);
        }
    }
}

// ---------------- launch ----------------
extern "C" void kernel_launch(void* const* d_in, const int* in_sizes, int n_in,
                              void* d_out, int out_size)
{
    const float* x          = (const float*)d_in[0];
    const float* mask       = (const float*)d_in[1];
    const float* w_qkv      = (const float*)d_in[2];
    const float* w_proj     = (const float*)d_in[3];
    const float* b_proj     = (const float*)d_in[4];
    const float* bias_table = (const float*)d_in[5];
    float* out = (float*)d_out;

    __half* qkv16 = 0;
    float*  bpre  = 0;
    __half* x16   = 0;
    __half* att16 = 0;
    __half* wq16  = 0;
    __half* wp16  = 0;
    cudaGetSymbolAddress((void**)&qkv16, g_qkv16);
    cudaGetSymbolAddress((void**)&bpre,  g_bias_pre);
    cudaGetSymbolAddress((void**)&x16,   g_x16);
    cudaGetSymbolAddress((void**)&att16, g_att16);
    cudaGetSymbolAddress((void**)&wq16,  g_wqkv16);
    cudaGetSymbolAddress((void**)&wp16,  g_wproj16);

    cudaFuncSetAttribute(attn_mma,
                         cudaFuncAttributeMaxDynamicSharedMemorySize, AT_SMEM);

    // 0) conversions + dense bias
    int n4 = (MROWS * DIMC) / 4;
    convert_f2h<<<(n4 + 255) / 256, 256>>>(x, x16, n4);
    int w4 = (DIMC * NQKV) / 4;
    convert_f2h<<<(w4 + 255) / 256, 256>>>(w_qkv, wq16, w4);
    int p4 = (DIMC * DIMC) / 4;
    convert_f2h<<<(p4 + 255) / 256, 256>>>(w_proj, wp16, p4);
    bias_pre_kernel<<<WTH, 256>>>(bias_table, bpre);

    // 1) QKV projection -> fp16
    hgemm128x64<true><<<dim3(NQKV / 64, MROWS / 128), 256>>>(
        x16, wq16, (const float*)0, qkv16, NQKV, DIMC);
    // 2) windowed attention (tensor-core, fp32 softmax) -> fp16
    attn_mma<<<WN_WINDOWS * HEADS, 512, AT_SMEM>>>(qkv16, mask, bpre, att16);
    // 3) output projection -> fp32 + bias
    hgemm128x64<false><<<dim3(DIMC / 64, MROWS / 128), 256>>>(
        att16, wp16, b_proj, out, DIMC, DIMC);
}

// round 17
// speedup vs baseline: 3.1043x; 1.0189x over previous
#include <cuda_runtime.h>
#include <cuda_fp16.h>
#include <cstdint>

typedef unsigned int u32;

// ---------------- problem constants ----------------
#define WN_WINDOWS 960
#define P_TOK      144
#define DIMC       192
#define HEADS      6
#define DH         32
#define NQKV       576          // 3*DIM
#define MROWS      138240       // 960*144
#define QK_SCALE   0.17677669529663687f   // 32^-0.5

#define BT_STRIDE  384
#define WTH        384          // 64 window types * 6 heads
#define PP         (P_TOK * P_TOK)   // 20736

// ---------------- scratch (static device globals; no alloc allowed) -----
__device__ __half g_qkv16[(size_t)MROWS * NQKV];   // (BN*P, 3*DIM) fp16
__device__ __half g_bias16[(size_t)WTH * PP];      // dense bias, fp16
__device__ __half g_mask16[(size_t)WN_WINDOWS * PP]; // mask, fp16
__device__ __half g_x16[(size_t)MROWS * DIMC];     // x in fp16
__device__ __half g_att16[(size_t)MROWS * DIMC];   // attention out fp16
__device__ __half g_wqkv16[(size_t)DIMC * NQKV];
__device__ __half g_wproj16[(size_t)DIMC * DIMC];

// ---------------- fp32 -> fp16 conversion (vectorized) ------------------
__global__ void convert_f2h(const float* __restrict__ in,
                            __half* __restrict__ out, int n4)
{
    int i = blockIdx.x * blockDim.x + threadIdx.x;
    if (i < n4) {
        float4 v = reinterpret_cast<const float4*>(in)[i];
        reinterpret_cast<__half2*>(out)[i * 2]     = __floats2half2_rn(v.x, v.y);
        reinterpret_cast<__half2*>(out)[i * 2 + 1] = __floats2half2_rn(v.z, v.w);
    }
}

// ---------------- mma helpers (fragment scheme verified R11/R16) --------
__device__ __forceinline__ void ldsm_x4(u32* r, u32 addr) {
    asm volatile("ldmatrix.sync.aligned.m8n8.x4.shared.b16 {%0,%1,%2,%3}, [%4];"
                 : "=r"(r[0]), "=r"(r[1]), "=r"(r[2]), "=r"(r[3]) : "r"(addr));
}
__device__ __forceinline__ void ldsm_x4_t(u32* r, u32 addr) {
    asm volatile("ldmatrix.sync.aligned.m8n8.x4.trans.shared.b16 {%0,%1,%2,%3}, [%4];"
                 : "=r"(r[0]), "=r"(r[1]), "=r"(r[2]), "=r"(r[3]) : "r"(addr));
}
__device__ __forceinline__ void mma16816(float* c, const u32* a, const u32* b) {
    asm volatile(
        "mma.sync.aligned.m16n8k16.row.col.f32.f16.f16.f32 "
        "{%0,%1,%2,%3}, {%4,%5,%6,%7}, {%8,%9}, {%0,%1,%2,%3};"
        : "+f"(c[0]), "+f"(c[1]), "+f"(c[2]), "+f"(c[3])
        : "r"(a[0]), "r"(a[1]), "r"(a[2]), "r"(a[3]), "r"(b[0]), "r"(b[1]));
}

// ---------------- fp16 GEMM: C[M,N] = A[M,K] @ B[K,N] (+bias) ----------
// BM=128, BN=64, BK=32, 256 threads = 8 warps. HOUT: store fp16 else fp32.
#define PADA 40   // As row stride (halfs)
#define PADB 72   // Bs row stride (halfs)

template <bool HOUT>
__global__ __launch_bounds__(256)
void hgemm128x64(const __half* __restrict__ A, const __half* __restrict__ B,
                 const float* __restrict__ bias, void* __restrict__ Cv,
                 int N, int K)
{
    __shared__ __half As[2][128 * PADA];
    __shared__ __half Bs[2][32 * PADB];

    const int tid  = threadIdx.x;
    const int lane = tid & 31;
    const int wid  = tid >> 5;
    const int warpM = (wid & 3) * 32;
    const int warpN = (wid >> 2) * 32;
    const int rowBase = blockIdx.y * 128;
    const int colBase = blockIdx.x * 64;

    const int aRow   = tid >> 2;
    const int aChunk = (tid & 3) * 8;
    const int bRow   = tid >> 3;
    const int bChunk = (tid & 7) * 8;

    const __half* Ag0 = A + (size_t)(rowBase + aRow) * K + aChunk;
    const __half* Ag1 = A + (size_t)(rowBase + aRow + 64) * K + aChunk;
    const __half* Bg  = B + (size_t)bRow * N + colBase + bChunk;

    float acc[2][4][4];
#pragma unroll
    for (int mt = 0; mt < 2; mt++)
#pragma unroll
        for (int nt = 0; nt < 4; nt++)
#pragma unroll
            for (int e = 0; e < 4; e++) acc[mt][nt][e] = 0.f;

    const int nTiles = K >> 5;

    {
        uint4 a0 = *reinterpret_cast<const uint4*>(Ag0);
        uint4 a1 = *reinterpret_cast<const uint4*>(Ag1);
        uint4 b0 = *reinterpret_cast<const uint4*>(Bg);
        *reinterpret_cast<uint4*>(&As[0][aRow * PADA + aChunk])        = a0;
        *reinterpret_cast<uint4*>(&As[0][(aRow + 64) * PADA + aChunk]) = a1;
        *reinterpret_cast<uint4*>(&Bs[0][bRow * PADB + bChunk])        = b0;
    }
    __syncthreads();

    for (int kt = 0; kt < nTiles; kt++) {
        const int buf = kt & 1;
        const bool hasNext = (kt + 1) < nTiles;
        uint4 na0, na1, nb0;
        if (hasNext) {
            const int k0 = (kt + 1) << 5;
            na0 = *reinterpret_cast<const uint4*>(Ag0 + k0);
            na1 = *reinterpret_cast<const uint4*>(Ag1 + k0);
            nb0 = *reinterpret_cast<const uint4*>(Bg + (size_t)k0 * N);
        }

        const u32 aBase = (u32)__cvta_generic_to_shared(&As[buf][0]);
        const u32 bBase = (u32)__cvta_generic_to_shared(&Bs[buf][0]);
        const int l15 = lane & 15;
        const int l16 = (lane >> 4) * 8;

#pragma unroll
        for (int ks = 0; ks < 32; ks += 16) {
            u32 af[2][4], bf[2][4];
#pragma unroll
            for (int mt = 0; mt < 2; mt++)
                ldsm_x4(af[mt], aBase +
                        (u32)((warpM + mt * 16 + l15) * PADA + ks + l16) * 2u);
#pragma unroll
            for (int ng = 0; ng < 2; ng++)
                ldsm_x4_t(bf[ng], bBase +
                          (u32)((ks + l15) * PADB + warpN + ng * 16 + l16) * 2u);
#pragma unroll
            for (int mt = 0; mt < 2; mt++)
#pragma unroll
                for (int nt = 0; nt < 4; nt++)
                    mma16816(acc[mt][nt], af[mt], &bf[nt >> 1][(nt & 1) * 2]);
        }

        if (hasNext) {
            const int nbuf = buf ^ 1;
            *reinterpret_cast<uint4*>(&As[nbuf][aRow * PADA + aChunk])        = na0;
            *reinterpret_cast<uint4*>(&As[nbuf][(aRow + 64) * PADA + aChunk]) = na1;
            *reinterpret_cast<uint4*>(&Bs[nbuf][bRow * PADB + bChunk])        = nb0;
        }
        __syncthreads();
    }

    const int rBase = rowBase + warpM + (lane >> 2);
    const int cBase = colBase + warpN + (lane & 3) * 2;
#pragma unroll
    for (int mt = 0; mt < 2; mt++) {
#pragma unroll
        for (int nt = 0; nt < 4; nt++) {
            int col = cBase + nt * 8;
            float b0 = 0.f, b1 = 0.f;
            if (bias) { b0 = bias[col]; b1 = bias[col + 1]; }
            int r0 = rBase + mt * 16;
            if (HOUT) {
                __half* C16 = (__half*)Cv;
                *reinterpret_cast<__half2*>(&C16[(size_t)r0 * N + col]) =
                    __floats2half2_rn(acc[mt][nt][0] + b0, acc[mt][nt][1] + b1);
                *reinterpret_cast<__half2*>(&C16[(size_t)(r0 + 8) * N + col]) =
                    __floats2half2_rn(acc[mt][nt][2] + b0, acc[mt][nt][3] + b1);
            } else {
                float* C = (float*)Cv;
                *reinterpret_cast<float2*>(&C[(size_t)r0 * N + col]) =
                    make_float2(acc[mt][nt][0] + b0, acc[mt][nt][1] + b1);
                *reinterpret_cast<float2*>(&C[(size_t)(r0 + 8) * N + col]) =
                    make_float2(acc[mt][nt][2] + b0, acc[mt][nt][3] + b1);
            }
        }
    }
}

// ---------------- bias precompute: (3312,64,6) -> dense fp16 ------------
__global__ __launch_bounds__(512)
void bias_pre_kernel(const float* __restrict__ bt, __half* __restrict__ outp)
{
    __shared__ int d1s[P_TOK], d2s[P_TOK];
    const int wh = blockIdx.x;
    const int tid = threadIdx.x;
    if (tid < P_TOK) {
        int z = tid / 72, rem = tid - z * 72;
        int hh = rem / 12, w = rem - hh * 12;
        d1s[tid] = z * 828 + hh * 23 + w;
        d2s[tid] = z * 1656 + hh * 138 - w;
    }
    __syncthreads();
    __half* o = outp + (size_t)wh * PP;
    for (int e = tid; e < PP; e += 512) {
        int i = e / P_TOK, j = e - i * P_TOK;
        o[e] = __float2half_rn(
            __ldg(&bt[(size_t)(d1s[i] + d2s[j] + 11) * BT_STRIDE + wh]));
    }
}

// ---------------- attention kernel: full tensor-core --------------------
// One block per (window, head). 512 threads = 16 warps.
#define QVPAD   40                      // q/k/v row stride in halfs
#define SPAD    152                     // S16 row stride in halfs
#define SMQ     0                       // 144*40 halfs = 11520 B
#define SMK     11520
#define SMV     23040
#define SMS32   34560                   // 144*144 floats = 82944 B
#define SMS16   117504                  // 144*152 halfs  = 43776 B
#define SMSINV  161280                  // 144 floats
#define AT_SMEM (161280 + 144 * 4)

__global__ __launch_bounds__(512, 1)
void attn_mma(const __half* __restrict__ qkv, const __half* __restrict__ mask,
              const __half* __restrict__ bias_pre, __half* __restrict__ out)
{
    extern __shared__ char smx[];
    __half* sq   = (__half*)(smx + SMQ);
    __half* sk   = (__half*)(smx + SMK);
    __half* sv   = (__half*)(smx + SMV);
    float*  S32  = (float*)(smx + SMS32);
    __half* S16  = (__half*)(smx + SMS16);
    float*  sinv = (float*)(smx + SMSINV);

    const int blk  = blockIdx.x;
    const int wn   = blk / HEADS;
    const int h    = blk - wn * HEADS;
    const int tid  = threadIdx.x;
    const int lane = tid & 31;
    const int wid  = tid >> 5;            // 0..15

    const int wt = (wn / 240) * 16 + (wn / 15) % 16;
    const __half* bpre  = bias_pre + (size_t)(wt * HEADS + h) * PP;
    const __half* maskw = mask + (size_t)wn * PP;

    // ---- load q,k,v (fp16): 144 rows x 32 halfs = 4 uint4 chunks/row ---
    for (int e = tid; e < P_TOK * 4; e += 512) {
        int p = e >> 2, c = (e & 3) * 8;
        const __half* base = qkv + ((size_t)wn * P_TOK + p) * NQKV + h * DH + c;
        uint4 vq = *reinterpret_cast<const uint4*>(base);
        uint4 vk = *reinterpret_cast<const uint4*>(base + DIMC);
        uint4 vv = *reinterpret_cast<const uint4*>(base + 2 * DIMC);
        *reinterpret_cast<uint4*>(&sq[p * QVPAD + c]) = vq;
        *reinterpret_cast<uint4*>(&sk[p * QVPAD + c]) = vk;
        *reinterpret_cast<uint4*>(&sv[p * QVPAD + c]) = vv;
    }
    __syncthreads();

    const u32 sqB = (u32)__cvta_generic_to_shared(sq);
    const u32 skB = (u32)__cvta_generic_to_shared(sk);
    const u32 svB = (u32)__cvta_generic_to_shared(sv);
    const u32 s16B = (u32)__cvta_generic_to_shared(S16);
    const int l15 = lane & 15;
    const int l16 = (lane >> 4) * 8;

    // ---- S = scale*q@k^T + bias + mask : 81 tiles of m16n16, k=32 ------
    // sk is [n][k] row-major => B fragment via NON-trans ldsm; pairs
    // (bf0,bf2)=n0-7, (bf1,bf3)=n8-15  (verified R16).
    for (int t = wid; t < 81; t += 16) {
        const int mt = (t / 9) * 16;
        const int nt = (t % 9) * 16;
        float acc[2][4];
#pragma unroll
        for (int g = 0; g < 2; g++)
#pragma unroll
            for (int e = 0; e < 4; e++) acc[g][e] = 0.f;

#pragma unroll
        for (int ks = 0; ks < 32; ks += 16) {
            u32 af[4], bf[4];
            ldsm_x4(af, sqB + (u32)((mt + l15) * QVPAD + ks + l16) * 2u);
            ldsm_x4(bf, skB + (u32)((nt + l15) * QVPAD + ks + l16) * 2u);
            u32 blo[2] = { bf[0], bf[2] };
            u32 bhi[2] = { bf[1], bf[3] };
            mma16816(acc[0], af, blo);
            mma16816(acc[1], af, bhi);
        }
        const int r0 = mt + (lane >> 2);
        const int c0 = nt + (lane & 3) * 2;
#pragma unroll
        for (int g = 0; g < 2; g++) {
            const int c = c0 + g * 8;
            float2 b0 = __half22float2(
                *reinterpret_cast<const __half2*>(&bpre[r0 * P_TOK + c]));
            float2 m0 = __half22float2(
                *reinterpret_cast<const __half2*>(&maskw[r0 * P_TOK + c]));
            float2 b1 = __half22float2(
                *reinterpret_cast<const __half2*>(&bpre[(r0 + 8) * P_TOK + c]));
            float2 m1 = __half22float2(
                *reinterpret_cast<const __half2*>(&maskw[(r0 + 8) * P_TOK + c]));
            S32[r0 * P_TOK + c]           = acc[g][0] * QK_SCALE + b0.x + m0.x;
            S32[r0 * P_TOK + c + 1]       = acc[g][1] * QK_SCALE + b0.y + m0.y;
            S32[(r0 + 8) * P_TOK + c]     = acc[g][2] * QK_SCALE + b1.x + m1.x;
            S32[(r0 + 8) * P_TOK + c + 1] = acc[g][3] * QK_SCALE + b1.y + m1.y;
        }
    }
    __syncthreads();

    // ---- softmax: store UNNORMALIZED exp to S16; 1/sum kept per row ----
    for (int i = wid; i < P_TOK; i += 16) {
        float mx = -3.4e38f;
        for (int j = lane; j < P_TOK; j += 32)
            mx = fmaxf(mx, S32[i * P_TOK + j]);
#pragma unroll
        for (int o = 16; o; o >>= 1)
            mx = fmaxf(mx, __shfl_xor_sync(0xffffffffu, mx, o));
        float sum = 0.f;
        for (int j = lane; j < P_TOK; j += 32) {
            float e = __expf(S32[i * P_TOK + j] - mx);
            sum += e;
            S16[i * SPAD + j] = __float2half_rn(e);
        }
#pragma unroll
        for (int o = 16; o; o >>= 1)
            sum += __shfl_xor_sync(0xffffffffu, sum, o);
        if (lane == 0) sinv[i] = 1.0f / sum;
    }
    __syncthreads();

    // ---- O = (E @ V) * sinv : 18 tiles of m16n16, k=144 ----------------
    for (int t = wid; t < 18; t += 16) {
        const int mt = (t >> 1) * 16;
        const int nt = (t & 1) * 16;
        float acc[2][4];
#pragma unroll
        for (int g = 0; g < 2; g++)
#pragma unroll
            for (int e = 0; e < 4; e++) acc[g][e] = 0.f;

#pragma unroll 1
        for (int ks = 0; ks < P_TOK; ks += 16) {
            u32 af[4], bf[4];
            ldsm_x4(af, s16B + (u32)((mt + l15) * SPAD + ks + l16) * 2u);
            ldsm_x4_t(bf, svB + (u32)((ks + l15) * QVPAD + nt + l16) * 2u);
            mma16816(acc[0], af, &bf[0]);
            mma16816(acc[1], af, &bf[2]);
        }
        const int r0 = mt + (lane >> 2);
        const int c0 = nt + (lane & 3) * 2;
        const float s0 = sinv[r0];
        const float s1 = sinv[r0 + 8];
        __half* o0 = out + ((size_t)wn * P_TOK + r0) * DIMC + h * DH;
        __half* o1 = out + ((size_t)wn * P_TOK + r0 + 8) * DIMC + h * DH;
#pragma unroll
        for (int g = 0; g < 2; g++) {
            const int c = c0 + g * 8;
            *reinterpret_cast<__half2*>(&o0[c]) =
                __floats2half2_rn(acc[g][0] * s0, acc[g][1] * s0);
            *reinterpret_cast<__half2*>(&o1[c]) =
                __floats2half2_rn(acc[g][2] * s1, acc[g][3] * s1);
        }
    }
}

// ---------------- launch ----------------
extern "C" void kernel_launch(void* const* d_in, const int* in_sizes, int n_in,
                              void* d_out, int out_size)
{
    const float* x          = (const float*)d_in[0];
    const float* mask       = (const float*)d_in[1];
    const float* w_qkv      = (const float*)d_in[2];
    const float* w_proj     = (const float*)d_in[3];
    const float* b_proj     = (const float*)d_in[4];
    const float* bias_table = (const float*)d_in[5];
    float* out = (float*)d_out;

    __half* qkv16 = 0;
    __half* b16   = 0;
    __half* m16   = 0;
    __half* x16   = 0;
    __half* att16 = 0;
    __half* wq16  = 0;
    __half* wp16  = 0;
    cudaGetSymbolAddress((void**)&qkv16, g_qkv16);
    cudaGetSymbolAddress((void**)&b16,   g_bias16);
    cudaGetSymbolAddress((void**)&m16,   g_mask16);
    cudaGetSymbolAddress((void**)&x16,   g_x16);
    cudaGetSymbolAddress((void**)&att16, g_att16);
    cudaGetSymbolAddress((void**)&wq16,  g_wqkv16);
    cudaGetSymbolAddress((void**)&wp16,  g_wproj16);

    cudaFuncSetAttribute(attn_mma,
                         cudaFuncAttributeMaxDynamicSharedMemorySize, AT_SMEM);

    // 0) conversions + dense bias
    int n4 = (MROWS * DIMC) / 4;
    convert_f2h<<<(n4 + 255) / 256, 256>>>(x, x16, n4);
    int w4 = (DIMC * NQKV) / 4;
    convert_f2h<<<(w4 + 255) / 256, 256>>>(w_qkv, wq16, w4);
    int p4 = (DIMC * DIMC) / 4;
    convert_f2h<<<(p4 + 255) / 256, 256>>>(w_proj, wp16, p4);
    int m4 = (WN_WINDOWS * PP) / 4;
    convert_f2h<<<(m4 + 255) / 256, 256>>>(mask, m16, m4);
    bias_pre_kernel<<<WTH, 512>>>(bias_table, b16);

    // 1) QKV projection -> fp16
    hgemm128x64<true><<<dim3(NQKV / 64, MROWS / 128), 256>>>(
        x16, wq16, (const float*)0, qkv16, NQKV, DIMC);
    // 2) windowed attention (tensor-core, fp32 softmax) -> fp16
    attn_mma<<<WN_WINDOWS * HEADS, 512, AT_SMEM>>>(qkv16, m16, b16, att16);
    // 3) output projection -> fp32 + bias
    hgemm128x64<false><<<dim3(DIMC / 64, MROWS / 128), 256>>>(
        att16, wp16, b_proj, out, DIMC, DIMC);
}